// round 1
// baseline (speedup 1.0000x reference)
#include <cuda_runtime.h>
#include <cstdint>

#define MAXG 1024
#define RESI 256

__device__ float4 d_g0[MAXG];   // mx, my, cA, cB   (cA,cB include -0.5*log2e)
__device__ float4 d_g1[MAXG];   // cC, opacity, mask bits (punned), 0

__device__ __forceinline__ float ex2f(float x) {
    float y;
    asm("ex2.approx.ftz.f32 %0, %1;" : "=f"(y) : "f"(x));
    return y;
}

// ---------------------------------------------------------------------------
// Preprocess: per-gaussian conic + tile masks (N threads total)
// ---------------------------------------------------------------------------
__global__ void prep_kernel(const float* __restrict__ xyz,
                            const float* __restrict__ scaling,
                            const float* __restrict__ rotation,
                            const float* __restrict__ opacity,
                            const float* __restrict__ rot,
                            int N) {
    int i = blockIdx.x * blockDim.x + threadIdx.x;
    if (i >= N) return;
    const float RES = (float)RESI;

    // quaternion -> rotation matrix (normalized)
    float qr = rotation[4 * i + 0];
    float qx = rotation[4 * i + 1];
    float qy = rotation[4 * i + 2];
    float qz = rotation[4 * i + 3];
    float inv = rsqrtf(qr * qr + qx * qx + qy * qy + qz * qz);
    qr *= inv; qx *= inv; qy *= inv; qz *= inv;

    float R00 = 1.f - 2.f * (qy * qy + qz * qz);
    float R01 = 2.f * (qx * qy - qr * qz);
    float R02 = 2.f * (qx * qz + qr * qy);
    float R10 = 2.f * (qx * qy + qr * qz);
    float R11 = 1.f - 2.f * (qx * qx + qz * qz);
    float R12 = 2.f * (qy * qz - qr * qx);
    float R20 = 2.f * (qx * qz - qr * qy);
    float R21 = 2.f * (qy * qz + qr * qx);
    float R22 = 1.f - 2.f * (qx * qx + qy * qy);

    float s0 = scaling[3 * i + 0];
    float s1 = scaling[3 * i + 1];
    float s2 = scaling[3 * i + 2];

    // L = R * diag-ish (scale columns)
    float L00 = R00 * s0, L01 = R01 * s1, L02 = R02 * s2;
    float L10 = R10 * s0, L11 = R11 * s1, L12 = R12 * s2;
    float L20 = R20 * s0, L21 = R21 * s1, L22 = R22 * s2;

    // C = L * L^T (symmetric)
    float C00 = L00 * L00 + L01 * L01 + L02 * L02;
    float C01 = L00 * L10 + L01 * L11 + L02 * L12;
    float C02 = L00 * L20 + L01 * L21 + L02 * L22;
    float C11 = L10 * L10 + L11 * L11 + L12 * L12;
    float C12 = L10 * L20 + L11 * L21 + L12 * L22;
    float C22 = L20 * L20 + L21 * L21 + L22 * L22;

    // A = diag(res,res,0) @ rot ; rows 0 and 1 only
    float a00 = RES * rot[0], a01 = RES * rot[1], a02 = RES * rot[2];
    float a10 = RES * rot[3], a11 = RES * rot[4], a12 = RES * rot[5];

    // cov2d = A C A^T (2x2 symmetric)
    float v0x = C00 * a00 + C01 * a01 + C02 * a02;
    float v0y = C01 * a00 + C11 * a01 + C12 * a02;
    float v0z = C02 * a00 + C12 * a01 + C22 * a02;
    float c00 = a00 * v0x + a01 * v0y + a02 * v0z;
    float c01 = a10 * v0x + a11 * v0y + a12 * v0z;
    float v1x = C00 * a10 + C01 * a11 + C02 * a12;
    float v1y = C01 * a10 + C11 * a11 + C12 * a12;
    float v1z = C02 * a10 + C12 * a11 + C22 * a12;
    float c11 = a10 * v1x + a11 * v1y + a12 * v1z;

    float det = c00 * c11 - c01 * c01;
    float mid = 0.5f * (c00 + c11);
    float sq = sqrtf(fmaxf(mid * mid - det, 0.1f));
    float lam = fmaxf(mid + sq, mid - sq);
    float radii = ceilf(3.0f * sqrtf(lam));

    float mx = xyz[3 * i + 0] * (RES * 0.5f);
    float my = xyz[3 * i + 1] * (RES * 0.5f);

    float rminx = fminf(fmaxf(mx - radii, 0.f), RES - 1.f);
    float rmaxx = fminf(fmaxf(mx + radii, 0.f), RES - 1.f);
    float rminy = fminf(fmaxf(my - radii, 0.f), RES - 1.f);
    float rmaxy = fminf(fmaxf(my + radii, 0.f), RES - 1.f);

    unsigned mw = 0u;
    #pragma unroll
    for (int t = 0; t < 16; t++) {
        float ts = (float)(t * 16);
        if (fminf(rmaxx, ts + 15.f) > fmaxf(rminx, ts)) mw |= (1u << t);
        if (fminf(rmaxy, ts + 15.f) > fmaxf(rminy, ts)) mw |= (1u << (16 + t));
    }

    float idet = 1.0f / det;
    const float L2E = 1.4426950408889634f;
    // power*log2e = cA*dx^2 + cB*dy^2 + cC*dx*dy
    float cA = -0.5f * L2E * (c11 * idet);
    float cB = -0.5f * L2E * (c00 * idet);
    float cC = -0.5f * L2E * (-2.0f * c01 * idet);

    d_g0[i] = make_float4(mx, my, cA, cB);
    d_g1[i] = make_float4(cC, opacity[i], __uint_as_float(mw), 0.f);
}

// ---------------------------------------------------------------------------
// Main splat: 128 CTAs x 128 threads, 4 horizontal pixels per thread.
// CTA covers a 32(w) x 16(h) region = two adjacent tiles, one tile row.
// ---------------------------------------------------------------------------
__global__ void __launch_bounds__(128) splat_kernel(float* __restrict__ out, int N) {
    __shared__ float4 s0[MAXG];
    __shared__ float4 s1[MAXG];

    int t = threadIdx.x;
    for (int i = t; i < N; i += 128) {
        s0[i] = d_g0[i];
        s1[i] = d_g1[i];
    }
    __syncthreads();

    int bid = blockIdx.x;
    int ty   = bid >> 3;          // tile row 0..15
    int pair = bid & 7;           // which pair of tiles horizontally
    int r  = t >> 3;              // row within tile 0..15
    int cg = t & 7;               // column group 0..7
    int xbase = pair * 32 + cg * 4;
    int y = ty * 16 + r;
    int tx = xbase >> 4;          // tile column of my 4 pixels
    int shx = tx;
    int shy = 16 + ty;

    float px = (float)xbase - 127.5f;
    float py = (float)y - 127.5f;

    float a0 = 0.f, a1 = 0.f, a2 = 0.f, a3 = 0.f;

    #pragma unroll 2
    for (int i = 0; i < N; i++) {
        float4 q1 = s1[i];
        unsigned mw = __float_as_uint(q1.z);
        if (!((mw >> shx) & (mw >> shy) & 1u)) continue;
        float4 q0 = s0[i];
        float dx = px - q0.x;
        float dy = py - q0.y;
        float h  = q1.x * dy;            // cC * dy
        float sB = q0.w * (dy * dy);     // cB * dy^2
        float o  = q1.y;

        float q, w;
        q = fmaf(dx, fmaf(q0.z, dx, h), sB);
        w = ex2f(q);
        a0 = fmaf(w, o, a0);

        float dxb = dx + 1.f;
        q = fmaf(dxb, fmaf(q0.z, dxb, h), sB);
        w = ex2f(q);
        a1 = fmaf(w, o, a1);

        float dxc = dx + 2.f;
        q = fmaf(dxc, fmaf(q0.z, dxc, h), sB);
        w = ex2f(q);
        a2 = fmaf(w, o, a2);

        float dxd = dx + 3.f;
        q = fmaf(dxd, fmaf(q0.z, dxd, h), sB);
        w = ex2f(q);
        a3 = fmaf(w, o, a3);
    }

    float4 res4 = make_float4(a0, a1, a2, a3);
    *reinterpret_cast<float4*>(out + y * RESI + xbase) = res4;
}

// ---------------------------------------------------------------------------
extern "C" void kernel_launch(void* const* d_in, const int* in_sizes, int n_in,
                              void* d_out, int out_size) {
    const float* xyz      = (const float*)d_in[0];
    const float* scaling  = (const float*)d_in[1];
    const float* rotation = (const float*)d_in[2];
    const float* opacity  = (const float*)d_in[3];
    const float* rot      = (const float*)d_in[4];
    // d_in[5] = res (256, fixed by problem shape)

    int N = in_sizes[0] / 3;
    if (N > MAXG) N = MAXG;

    prep_kernel<<<(N + 127) / 128, 128>>>(xyz, scaling, rotation, opacity, rot, N);
    splat_kernel<<<128, 128>>>((float*)d_out, N);
}

// round 2
// speedup vs baseline: 2.6693x; 2.6693x over previous
#include <cuda_runtime.h>
#include <cstdint>

#define MAXG 1024
#define RESI 256
#define GSPLIT 8
#define GCHUNK 128   // MAXG / GSPLIT

__device__ float4 d_g0[MAXG];   // mx, my, cA, cB   (cA,cB include -0.5*log2e)
__device__ float4 d_g1[MAXG];   // cC, opacity, mask bits (punned), 0
__device__ float  d_partial[GSPLIT * RESI * RESI];   // 2 MB scratch

__device__ __forceinline__ float ex2f(float x) {
    float y;
    asm("ex2.approx.ftz.f32 %0, %1;" : "=f"(y) : "f"(x));
    return y;
}

// ---------------------------------------------------------------------------
// Preprocess: per-gaussian conic + tile masks (N threads total)
// ---------------------------------------------------------------------------
__global__ void prep_kernel(const float* __restrict__ xyz,
                            const float* __restrict__ scaling,
                            const float* __restrict__ rotation,
                            const float* __restrict__ opacity,
                            const float* __restrict__ rot,
                            int N) {
    int i = blockIdx.x * blockDim.x + threadIdx.x;
    if (i >= N) return;
    const float RES = (float)RESI;

    float qr = rotation[4 * i + 0];
    float qx = rotation[4 * i + 1];
    float qy = rotation[4 * i + 2];
    float qz = rotation[4 * i + 3];
    float inv = rsqrtf(qr * qr + qx * qx + qy * qy + qz * qz);
    qr *= inv; qx *= inv; qy *= inv; qz *= inv;

    float R00 = 1.f - 2.f * (qy * qy + qz * qz);
    float R01 = 2.f * (qx * qy - qr * qz);
    float R02 = 2.f * (qx * qz + qr * qy);
    float R10 = 2.f * (qx * qy + qr * qz);
    float R11 = 1.f - 2.f * (qx * qx + qz * qz);
    float R12 = 2.f * (qy * qz - qr * qx);
    float R20 = 2.f * (qx * qz - qr * qy);
    float R21 = 2.f * (qy * qz + qr * qx);
    float R22 = 1.f - 2.f * (qx * qx + qy * qy);

    float s0 = scaling[3 * i + 0];
    float s1 = scaling[3 * i + 1];
    float s2 = scaling[3 * i + 2];

    float L00 = R00 * s0, L01 = R01 * s1, L02 = R02 * s2;
    float L10 = R10 * s0, L11 = R11 * s1, L12 = R12 * s2;
    float L20 = R20 * s0, L21 = R21 * s1, L22 = R22 * s2;

    float C00 = L00 * L00 + L01 * L01 + L02 * L02;
    float C01 = L00 * L10 + L01 * L11 + L02 * L12;
    float C02 = L00 * L20 + L01 * L21 + L02 * L22;
    float C11 = L10 * L10 + L11 * L11 + L12 * L12;
    float C12 = L10 * L20 + L11 * L21 + L12 * L22;
    float C22 = L20 * L20 + L21 * L21 + L22 * L22;

    float a00 = RES * rot[0], a01 = RES * rot[1], a02 = RES * rot[2];
    float a10 = RES * rot[3], a11 = RES * rot[4], a12 = RES * rot[5];

    float v0x = C00 * a00 + C01 * a01 + C02 * a02;
    float v0y = C01 * a00 + C11 * a01 + C12 * a02;
    float v0z = C02 * a00 + C12 * a01 + C22 * a02;
    float c00 = a00 * v0x + a01 * v0y + a02 * v0z;
    float c01 = a10 * v0x + a11 * v0y + a12 * v0z;
    float v1x = C00 * a10 + C01 * a11 + C02 * a12;
    float v1y = C01 * a10 + C11 * a11 + C12 * a12;
    float v1z = C02 * a10 + C12 * a11 + C22 * a12;
    float c11 = a10 * v1x + a11 * v1y + a12 * v1z;

    float det = c00 * c11 - c01 * c01;
    float mid = 0.5f * (c00 + c11);
    float sq = sqrtf(fmaxf(mid * mid - det, 0.1f));
    float lam = fmaxf(mid + sq, mid - sq);
    float radii = ceilf(3.0f * sqrtf(lam));

    float mx = xyz[3 * i + 0] * (RES * 0.5f);
    float my = xyz[3 * i + 1] * (RES * 0.5f);

    float rminx = fminf(fmaxf(mx - radii, 0.f), RES - 1.f);
    float rmaxx = fminf(fmaxf(mx + radii, 0.f), RES - 1.f);
    float rminy = fminf(fmaxf(my - radii, 0.f), RES - 1.f);
    float rmaxy = fminf(fmaxf(my + radii, 0.f), RES - 1.f);

    unsigned mw = 0u;
    #pragma unroll
    for (int t = 0; t < 16; t++) {
        float ts = (float)(t * 16);
        if (fminf(rmaxx, ts + 15.f) > fmaxf(rminx, ts)) mw |= (1u << t);
        if (fminf(rmaxy, ts + 15.f) > fmaxf(rminy, ts)) mw |= (1u << (16 + t));
    }

    float idet = 1.0f / det;
    const float L2E = 1.4426950408889634f;
    float cA = -0.5f * L2E * (c11 * idet);
    float cB = -0.5f * L2E * (c00 * idet);
    float cC = -0.5f * L2E * (-2.0f * c01 * idet);

    d_g0[i] = make_float4(mx, my, cA, cB);
    d_g1[i] = make_float4(cC, opacity[i], __uint_as_float(mw), 0.f);
}

// ---------------------------------------------------------------------------
// Splat: grid = 128 pixel-blocks x GSPLIT.  CTA covers 16(w) x 32(h) pixels
// and GCHUNK gaussians.  128 threads, 4 horizontal px each.
// Each warp = 8 rows x 4 colgroups -> entirely inside ONE 16x16 tile, so the
// tile-mask test is warp-uniform and culled gaussians are truly skipped.
// ---------------------------------------------------------------------------
__global__ void __launch_bounds__(128) splat_kernel(int N) {
    __shared__ float4 s0[GCHUNK];
    __shared__ float4 s1[GCHUNK];

    int bid = blockIdx.x;
    int s   = bid & (GSPLIT - 1);   // gaussian split
    int blk = bid >> 3;             // pixel block 0..127

    int g0 = s * GCHUNK;
    int gN = N - g0;
    if (gN > GCHUNK) gN = GCHUNK;

    int t = threadIdx.x;
    if (t < GCHUNK && t < gN) {
        s0[t] = d_g0[g0 + t];
        s1[t] = d_g1[g0 + t];
    }
    __syncthreads();

    int bx = blk & 15;              // tile column 0..15
    int by = blk >> 4;              // block row 0..7 (each 32px tall)
    int cg  = t & 3;
    int row = t >> 2;               // 0..31
    int x = bx * 16 + cg * 4;
    int y = by * 32 + row;
    unsigned need = (1u << bx) | (1u << (16 + (y >> 4)));

    float px = (float)x - 127.5f;
    float py = (float)y - 127.5f;

    float a0 = 0.f, a1 = 0.f, a2 = 0.f, a3 = 0.f;

    for (int i = 0; i < gN; i++) {
        float4 q1 = s1[i];
        unsigned mw = __float_as_uint(q1.z);
        if ((mw & need) != need) continue;   // warp-uniform skip
        float4 q0 = s0[i];
        float dx = px - q0.x;
        float dy = py - q0.y;
        float h  = q1.x * dy;                // cC * dy
        float sB = q0.w * (dy * dy);         // cB * dy^2
        float o  = q1.y;

        float q, w;
        q = fmaf(dx, fmaf(q0.z, dx, h), sB);
        w = ex2f(q);
        a0 = fmaf(w, o, a0);

        float dxb = dx + 1.f;
        q = fmaf(dxb, fmaf(q0.z, dxb, h), sB);
        w = ex2f(q);
        a1 = fmaf(w, o, a1);

        float dxc = dx + 2.f;
        q = fmaf(dxc, fmaf(q0.z, dxc, h), sB);
        w = ex2f(q);
        a2 = fmaf(w, o, a2);

        float dxd = dx + 3.f;
        q = fmaf(dxd, fmaf(q0.z, dxd, h), sB);
        w = ex2f(q);
        a3 = fmaf(w, o, a3);
    }

    float4* p = reinterpret_cast<float4*>(&d_partial[s * (RESI * RESI) + y * RESI + x]);
    *p = make_float4(a0, a1, a2, a3);
}

// ---------------------------------------------------------------------------
// Reduce: sum the GSPLIT partial images (fixed order -> deterministic).
// 16384 threads, one float4 (4 px) each.
// ---------------------------------------------------------------------------
__global__ void __launch_bounds__(256) reduce_kernel(float* __restrict__ out) {
    int i = blockIdx.x * blockDim.x + threadIdx.x;   // 0..16383
    const float4* p = reinterpret_cast<const float4*>(d_partial);
    float4 a = p[i];
    #pragma unroll
    for (int s = 1; s < GSPLIT; s++) {
        float4 b = p[s * (RESI * RESI / 4) + i];
        a.x += b.x; a.y += b.y; a.z += b.z; a.w += b.w;
    }
    reinterpret_cast<float4*>(out)[i] = a;
}

// ---------------------------------------------------------------------------
extern "C" void kernel_launch(void* const* d_in, const int* in_sizes, int n_in,
                              void* d_out, int out_size) {
    const float* xyz      = (const float*)d_in[0];
    const float* scaling  = (const float*)d_in[1];
    const float* rotation = (const float*)d_in[2];
    const float* opacity  = (const float*)d_in[3];
    const float* rot      = (const float*)d_in[4];

    int N = in_sizes[0] / 3;
    if (N > MAXG) N = MAXG;

    prep_kernel<<<(N + 127) / 128, 128>>>(xyz, scaling, rotation, opacity, rot, N);
    splat_kernel<<<128 * GSPLIT, 128>>>(N);
    reduce_kernel<<<RESI * RESI / 4 / 256, 256>>>((float*)d_out);
}